// round 1
// baseline (speedup 1.0000x reference)
#include <cuda_runtime.h>
#include <math.h>
#include <float.h>

#define N 384
#define NPIX (N*N)

// Scratch (no allocations allowed) — M/IRIL reused sequentially per scale.
__device__ float g_inp[NPIX];
__device__ float g_g[NPIX];
__device__ float g_M[NPIX];
__device__ float g_IRIL[NPIX];

__device__ __forceinline__ int refl(int i) {
    // jnp.pad 'reflect': -1 -> 1, N -> N-2. Offsets here are <= 33 < N, so one fold suffices.
    if (i < 0) i = -i;
    if (i >= N) i = 2 * N - 2 - i;
    return i;
}

// ---------------------------------------------------------------------------
// prep: inp = 255*x ;  g = gaussian3x3(inp) + 1  (reflect pad 1)
// ---------------------------------------------------------------------------
__global__ void prep_kernel(const float* __restrict__ x) {
    int idx = blockIdx.x * blockDim.x + threadIdx.x;
    if (idx >= NPIX) return;
    int iy = idx / N, ix = idx % N;
    g_inp[idx] = x[idx] * 255.0f;

    const float kw[3] = {1.0f, 2.0f, 1.0f};
    float acc = 0.0f;
#pragma unroll
    for (int dy = -1; dy <= 1; dy++) {
        int yy = refl(iy + dy);
#pragma unroll
        for (int dx = -1; dx <= 1; dx++) {
            int xx = refl(ix + dx);
            acc += kw[dy + 1] * kw[dx + 1] * x[yy * N + xx];
        }
    }
    // gaussian applied to inp = 255*x, kernel /16, then +1
    g_g[idx] = acc * (255.0f / 16.0f) + 1.0f;
}

// ---------------------------------------------------------------------------
// ordavg<S>: per output pixel, scan the SxS reflect-padded window once:
//   - maintain sorted-ascending top-9 in registers (t[0] = current min)
//   - accumulate box sum
// Writes M = mean(top9) and IRIL = M - boxmean.
// ---------------------------------------------------------------------------
template <int S>
__global__ void ordavg_kernel() {
    constexpr int P = S / 2;
    constexpr int T = 16 + 2 * P;
    __shared__ float tile[T][T];

    const int bx0 = blockIdx.x * 16;
    const int by0 = blockIdx.y * 16;
    const int tid = threadIdx.y * 16 + threadIdx.x;

    // Cooperative halo load with reflect indexing.
    for (int i = tid; i < T * T; i += 256) {
        int ty = i / T, tx = i % T;
        int gy = refl(by0 - P + ty);
        int gx = refl(bx0 - P + tx);
        tile[ty][tx] = g_inp[gy * N + gx];
    }
    __syncthreads();

    float t[9];
#pragma unroll
    for (int i = 0; i < 9; i++) t[i] = -FLT_MAX;
    float sum = 0.0f;

    const int ty = threadIdx.y, tx = threadIdx.x;
    for (int wy = 0; wy < S; wy++) {
        for (int wx = 0; wx < S; wx++) {
            float v = tile[ty + wy][tx + wx];
            sum += v;
            if (v > t[0]) {
                t[0] = v;
#pragma unroll
                for (int i = 0; i < 8; i++) {
                    if (t[i] > t[i + 1]) {
                        float tmp = t[i]; t[i] = t[i + 1]; t[i + 1] = tmp;
                    } else break;
                }
            }
        }
    }

    float M = ((t[0] + t[1]) + (t[2] + t[3]) + (t[4] + t[5]) + (t[6] + t[7]) + t[8]) / 9.0f;
    float avg = sum * (1.0f / (float)(S * S));
    int o = (by0 + ty) * N + (bx0 + tx);
    g_M[o] = M;
    g_IRIL[o] = M - avg;
}

// ---------------------------------------------------------------------------
// combine<D>: BE = max over 8 D-displaced neighbors of M (reflect);
// SLCM = max((BE/g - 1)*g, 0);
// WT = IRIL center, ni8 = 8 D-displaced IRIL neighbors;
// WD = max(WT - max(ni8), 0); WB = max(std(ni8, ddof=1), 5);
// cand = SLCM * WT * WD / WB ; out = first ? cand : max(out, cand)
// ---------------------------------------------------------------------------
template <int D, int FIRST>
__global__ void combine_kernel(float* __restrict__ out) {
    int idx = blockIdx.x * blockDim.x + threadIdx.x;
    if (idx >= NPIX) return;
    int iy = idx / N, ix = idx % N;

    float gg = g_g[idx];

    float BE = -FLT_MAX;
    float ni[9];
#pragma unroll
    for (int i = 0; i < 3; i++) {
        int yy = refl(iy + (i - 1) * D);
#pragma unroll
        for (int j = 0; j < 3; j++) {
            int xx = refl(ix + (j - 1) * D);
            int o = yy * N + xx;
            ni[i * 3 + j] = g_IRIL[o];
            if (!(i == 1 && j == 1)) BE = fmaxf(BE, g_M[o]);
        }
    }

    float SLCM = fmaxf((BE / gg - 1.0f) * gg, 0.0f);

    float WT = ni[4];
    float mx = -FLT_MAX;
    float s = 0.0f;
#pragma unroll
    for (int k = 0; k < 9; k++) {
        if (k == 4) continue;
        mx = fmaxf(mx, ni[k]);
        s += ni[k];
    }
    float mean = s * 0.125f;
    float ss = 0.0f;
#pragma unroll
    for (int k = 0; k < 9; k++) {
        if (k == 4) continue;
        float d = ni[k] - mean;
        ss += d * d;
    }
    float WB = fmaxf(sqrtf(ss * (1.0f / 7.0f)), 5.0f);
    float WD = fmaxf(WT - mx, 0.0f);
    float W = WT * WD / WB;
    float cand = SLCM * W;

    if (FIRST) out[idx] = cand;
    else       out[idx] = fmaxf(out[idx], cand);
}

// ---------------------------------------------------------------------------
extern "C" void kernel_launch(void* const* d_in, const int* in_sizes, int n_in,
                              void* d_out, int out_size) {
    const float* x = (const float*)d_in[0];
    float* out = (float*)d_out;

    prep_kernel<<<(NPIX + 255) / 256, 256>>>(x);

    dim3 blk(16, 16), grd(N / 16, N / 16);
    const int PB = 256, PG = (NPIX + PB - 1) / PB;

    ordavg_kernel<3><<<grd, blk>>>();
    combine_kernel<3, 1><<<PG, PB>>>(out);

    ordavg_kernel<5><<<grd, blk>>>();
    combine_kernel<5, 0><<<PG, PB>>>(out);

    ordavg_kernel<23><<<grd, blk>>>();
    combine_kernel<23, 0><<<PG, PB>>>(out);

    ordavg_kernel<33><<<grd, blk>>>();
    combine_kernel<33, 0><<<PG, PB>>>(out);
}

// round 2
// speedup vs baseline: 3.4275x; 3.4275x over previous
#include <cuda_runtime.h>
#include <math.h>
#include <float.h>

#define N 384
#define NPIX (N*N)

// Scratch (no allocations allowed). Planes reused sequentially per scale.
__device__ float g_inp[NPIX];
__device__ float g_g[NPIX];
__device__ float g_M[NPIX];
__device__ float g_IRIL[NPIX];
__device__ float g_plane[9][NPIX];   // column-wise top-9, descending in plane index
__device__ float g_colsum[NPIX];

__device__ __forceinline__ int refl(int i) {
    // jnp 'reflect': -1 -> 1, N -> N-2. Offsets <= 33 < N, one fold suffices.
    if (i < 0) i = -i;
    if (i >= N) i = 2 * N - 2 - i;
    return i;
}

// Ascending top-9 register heap: t[0] = current 9th-largest (min of kept set).
__device__ __forceinline__ void ins9(float (&t)[9], float v) {
    if (v > t[0]) {
        t[0] = v;
#pragma unroll
        for (int i = 0; i < 8; i++) {
            if (t[i] > t[i + 1]) { float tmp = t[i]; t[i] = t[i + 1]; t[i + 1] = tmp; }
            else break;
        }
    }
}

// ---------------------------------------------------------------------------
// prep: inp = 255*x ;  g = gaussian3x3(inp) + 1  (reflect pad 1)
// ---------------------------------------------------------------------------
__global__ void prep_kernel(const float* __restrict__ x) {
    int idx = blockIdx.x * blockDim.x + threadIdx.x;
    if (idx >= NPIX) return;
    int iy = idx / N, ix = idx % N;
    g_inp[idx] = x[idx] * 255.0f;

    const float kw[3] = {1.0f, 2.0f, 1.0f};
    float acc = 0.0f;
#pragma unroll
    for (int dy = -1; dy <= 1; dy++) {
        int yy = refl(iy + dy);
#pragma unroll
        for (int dx = -1; dx <= 1; dx++) {
            int xx = refl(ix + dx);
            acc += kw[dy + 1] * kw[dx + 1] * x[yy * N + xx];
        }
    }
    g_g[idx] = acc * (255.0f / 16.0f) + 1.0f;
}

// ---------------------------------------------------------------------------
// Pass 1: vertical strip (1 x S, reflect rows): sorted top-9 + sum.
// Planes stored DESCENDING (plane 0 = column max) for pass-2 early break.
// ---------------------------------------------------------------------------
template <int S>
__global__ void colpass_kernel() {
    constexpr int P = S / 2;
    int idx = blockIdx.x * blockDim.x + threadIdx.x;
    if (idx >= NPIX) return;
    int iy = idx / N, ix = idx % N;

    float t[9];
#pragma unroll
    for (int i = 0; i < 9; i++) t[i] = -FLT_MAX;
    float sum = 0.0f;

#pragma unroll
    for (int dy = -P; dy <= P; dy++) {
        int yy = refl(iy + dy);
        float v = g_inp[yy * N + ix];
        sum += v;
        ins9(t, v);
    }

#pragma unroll
    for (int p = 0; p < 9; p++) g_plane[p][idx] = t[8 - p];
    g_colsum[idx] = sum;
}

// ---------------------------------------------------------------------------
// Pass 2: merge S sorted column lists horizontally (reflect cols) with early
// break; separable box mean from column sums. Writes M and IRIL.
// ---------------------------------------------------------------------------
template <int S>
__global__ void rowpass_kernel() {
    constexpr int P = S / 2;
    int idx = blockIdx.x * blockDim.x + threadIdx.x;
    if (idx >= NPIX) return;
    int iy = idx / N, ix = idx % N;

    float t[9];
#pragma unroll
    for (int i = 0; i < 9; i++) t[i] = -FLT_MAX;
    float sum = 0.0f;

    for (int dx = -P; dx <= P; dx++) {
        int o = iy * N + refl(ix + dx);
        sum += g_colsum[o];
#pragma unroll
        for (int p = 0; p < 9; p++) {
            float v = g_plane[p][o];
            if (v > t[0]) {
                t[0] = v;
#pragma unroll
                for (int i = 0; i < 8; i++) {
                    if (t[i] > t[i + 1]) { float tmp = t[i]; t[i] = t[i + 1]; t[i + 1] = tmp; }
                    else break;
                }
            } else break;   // column list is descending: rest can't qualify
        }
    }

    float M = ((t[0] + t[1]) + (t[2] + t[3]) + (t[4] + t[5]) + (t[6] + t[7]) + t[8]) * (1.0f / 9.0f);
    float avg = sum * (1.0f / (float)(S * S));
    g_M[idx] = M;
    g_IRIL[idx] = M - avg;
}

// ---------------------------------------------------------------------------
// combine<D, FIRST>: BE/SLCM from M, W from IRIL neighbors; max-accumulate.
// FIRST also clamps at 0 (scale-3 branch is identically zero -> max with 0).
// ---------------------------------------------------------------------------
template <int D, int FIRST>
__global__ void combine_kernel(float* __restrict__ out) {
    int idx = blockIdx.x * blockDim.x + threadIdx.x;
    if (idx >= NPIX) return;
    int iy = idx / N, ix = idx % N;

    float gg = g_g[idx];

    float BE = -FLT_MAX;
    float ni[9];
#pragma unroll
    for (int i = 0; i < 3; i++) {
        int yy = refl(iy + (i - 1) * D);
#pragma unroll
        for (int j = 0; j < 3; j++) {
            int xx = refl(ix + (j - 1) * D);
            int o = yy * N + xx;
            ni[i * 3 + j] = g_IRIL[o];
            if (!(i == 1 && j == 1)) BE = fmaxf(BE, g_M[o]);
        }
    }

    float SLCM = fmaxf((BE / gg - 1.0f) * gg, 0.0f);

    float WT = ni[4];
    float mx = -FLT_MAX;
    float s = 0.0f;
#pragma unroll
    for (int k = 0; k < 9; k++) {
        if (k == 4) continue;
        mx = fmaxf(mx, ni[k]);
        s += ni[k];
    }
    float mean = s * 0.125f;
    float ss = 0.0f;
#pragma unroll
    for (int k = 0; k < 9; k++) {
        if (k == 4) continue;
        float d = ni[k] - mean;
        ss += d * d;
    }
    float WB = fmaxf(sqrtf(ss * (1.0f / 7.0f)), 5.0f);
    float WD = fmaxf(WT - mx, 0.0f);
    float cand = SLCM * WT * WD / WB;

    if (FIRST) out[idx] = fmaxf(cand, 0.0f);     // scale-3 contributes exactly 0
    else       out[idx] = fmaxf(out[idx], cand);
}

// ---------------------------------------------------------------------------
extern "C" void kernel_launch(void* const* d_in, const int* in_sizes, int n_in,
                              void* d_out, int out_size) {
    const float* x = (const float*)d_in[0];
    float* out = (float*)d_out;

    const int PB = 256, PG = (NPIX + PB - 1) / PB;

    prep_kernel<<<PG, PB>>>(x);

    colpass_kernel<5><<<PG, PB>>>();
    rowpass_kernel<5><<<PG, PB>>>();
    combine_kernel<5, 1><<<PG, PB>>>(out);

    colpass_kernel<23><<<PG, PB>>>();
    rowpass_kernel<23><<<PG, PB>>>();
    combine_kernel<23, 0><<<PG, PB>>>(out);

    colpass_kernel<33><<<PG, PB>>>();
    rowpass_kernel<33><<<PG, PB>>>();
    combine_kernel<33, 0><<<PG, PB>>>(out);
}